// round 5
// baseline (speedup 1.0000x reference)
#include <cuda_runtime.h>

#define NN   50000
#define NE   800000
#define FIN  96
#define FH   64
#define FOUT 40
#define N1   128   // FH*2  (cols 0-63: W1_0 path, 64-127: W1_1 path)
#define N2   80    // FOUT*2
#define SCAN_B 1024
#define NBLK_SCAN ((NN + SCAN_B - 1) / SCAN_B)   // 49

// Scratch (device globals: no allocations allowed)
__device__ __align__(16) float g_C1[NN * N1];   // [h_pre | y1]
__device__ __align__(16) float g_H[NN * FH];    // relu(h_pre + A_norm y1)
__device__ __align__(16) float g_y2[NN * FOUT]; // h @ W2_1
__device__ float g_dis[NN];                     // deg^{-1/2}
__device__ int   g_deg[NN];
__device__ int   g_off[NN];                     // CSR row offsets
__device__ int   g_cur[NN];                     // bucket cursors
__device__ int   g_bsum[NBLK_SCAN];
__device__ int   g_col[NE];                     // CSR col indices
__device__ float g_w[NE];                       // CSR edge weights
__device__ int   g_is64;                        // 1 if edge_index is int64, 0 if int32

// ---------------- edge_index dtype detection + access ----------------
__global__ void k_detect(const void* ei) {
    if (threadIdx.x == 0) {
        const unsigned long long* p = (const unsigned long long*)ei;
        int ok64 = 1;
        for (int i = 0; i < 64; i++) {
            if (p[i] >= (unsigned long long)NN) { ok64 = 0; break; }
        }
        g_is64 = ok64;
    }
}

__device__ __forceinline__ int edge_at(const void* ei, int which, int e) {
    if (g_is64) return (int)((const long long*)ei)[(size_t)which * NE + e];
    return ((const int*)ei)[(size_t)which * NE + e];
}

// ---------------- init / degree ----------------
__global__ void k_zero() {
    int i = blockIdx.x * blockDim.x + threadIdx.x;
    if (i < NN) { g_deg[i] = 0; g_cur[i] = 0; }
}

__global__ void k_deg(const void* __restrict__ ei) {
    int e = blockIdx.x * blockDim.x + threadIdx.x;
    if (e < NE) {
        int r = edge_at(ei, 0, e);
        if ((unsigned)r < NN) atomicAdd(&g_deg[r], 1);
    }
}

__global__ void k_dis() {
    int i = blockIdx.x * blockDim.x + threadIdx.x;
    if (i < NN) {
        int d = g_deg[i];
        g_dis[i] = (d > 0) ? rsqrtf((float)d) : 0.f;
    }
}

// ---------------- 3-phase exclusive scan of deg -> off ----------------
__global__ __launch_bounds__(SCAN_B) void k_scanA() {
    __shared__ int s[SCAN_B];
    int i = blockIdx.x * SCAN_B + threadIdx.x;
    int v = (i < NN) ? g_deg[i] : 0;
    s[threadIdx.x] = v;
    __syncthreads();
#pragma unroll
    for (int off = 1; off < SCAN_B; off <<= 1) {
        int t = (threadIdx.x >= off) ? s[threadIdx.x - off] : 0;
        __syncthreads();
        s[threadIdx.x] += t;
        __syncthreads();
    }
    if (i < NN) g_off[i] = s[threadIdx.x] - v;   // exclusive
    if (threadIdx.x == SCAN_B - 1) g_bsum[blockIdx.x] = s[SCAN_B - 1];
}

__global__ void k_scanB() {
    int lane = threadIdx.x;
    int v0 = (lane < NBLK_SCAN) ? g_bsum[lane] : 0;
    int v1 = (32 + lane < NBLK_SCAN) ? g_bsum[32 + lane] : 0;
    int s0 = v0;
#pragma unroll
    for (int o = 1; o < 32; o <<= 1) {
        int t = __shfl_up_sync(0xffffffffu, s0, o);
        if (lane >= o) s0 += t;
    }
    int tot0 = __shfl_sync(0xffffffffu, s0, 31);
    int s1 = v1;
#pragma unroll
    for (int o = 1; o < 32; o <<= 1) {
        int t = __shfl_up_sync(0xffffffffu, s1, o);
        if (lane >= o) s1 += t;
    }
    if (lane < NBLK_SCAN) g_bsum[lane] = s0 - v0;
    if (32 + lane < NBLK_SCAN) g_bsum[32 + lane] = tot0 + s1 - v1;
}

__global__ void k_scanC() {
    int i = blockIdx.x * blockDim.x + threadIdx.x;
    if (i < NN) g_off[i] += g_bsum[i / SCAN_B];
}

// ---------------- bucket edges into CSR ----------------
__global__ void k_bucket(const void* __restrict__ ei) {
    int e = blockIdx.x * blockDim.x + threadIdx.x;
    if (e >= NE) return;
    int r = edge_at(ei, 0, e);
    int c = edge_at(ei, 1, e);
    if ((unsigned)r >= NN || (unsigned)c >= NN) return;
    int slot = g_off[r] + atomicAdd(&g_cur[r], 1);
    g_col[slot] = c;
    g_w[slot]   = -g_dis[r] * g_dis[c];
}

// ---------------- GEMM1: C1[NN x 128] = x[NN x 96] @ [W1_0 | W1_1], +b1 on cols<64 ----
__global__ __launch_bounds__(256) void k_gemm1(const float* __restrict__ x,
                                               const float* __restrict__ W0,
                                               const float* __restrict__ W1,
                                               const float* __restrict__ b1) {
    __shared__ float ws[32][N1];   // 16 KB
    __shared__ float xs[64][32];   // 8 KB
    const int t  = threadIdx.x;
    const int cg = t & 31;
    const int rg = t >> 5;
    const int r0 = blockIdx.x * 64;

    float acc[8][4];
#pragma unroll
    for (int i = 0; i < 8; i++)
#pragma unroll
        for (int j = 0; j < 4; j++) acc[i][j] = 0.f;

    for (int kc = 0; kc < FIN; kc += 32) {
        for (int idx = t; idx < 32 * FH; idx += 256) {
            int kk = idx >> 6;
            int j  = idx & 63;
            int gk = kc + kk;
            ws[kk][j]      = W0[gk * FH + j];
            ws[kk][64 + j] = W1[gk * FH + j];
        }
        for (int idx = t; idx < 512; idx += 256) {
            int r  = idx >> 3;
            int c4 = idx & 7;
            int row = r0 + r;
            float4 v = make_float4(0.f, 0.f, 0.f, 0.f);
            if (row < NN) v = *(const float4*)&x[row * FIN + kc + c4 * 4];
            *(float4*)&xs[r][c4 * 4] = v;
        }
        __syncthreads();
#pragma unroll 8
        for (int k = 0; k < 32; k++) {
            float4 w = *(const float4*)&ws[k][cg * 4];
#pragma unroll
            for (int i = 0; i < 8; i++) {
                float a = xs[rg * 8 + i][k];
                acc[i][0] += a * w.x; acc[i][1] += a * w.y;
                acc[i][2] += a * w.z; acc[i][3] += a * w.w;
            }
        }
        __syncthreads();
    }

    const int col = cg * 4;
    float4 bb = make_float4(0.f, 0.f, 0.f, 0.f);
    if (col < FH) bb = *(const float4*)&b1[col];
#pragma unroll
    for (int i = 0; i < 8; i++) {
        int row = r0 + rg * 8 + i;
        if (row < NN) {
            float4 v = make_float4(acc[i][0] + bb.x, acc[i][1] + bb.y,
                                   acc[i][2] + bb.z, acc[i][3] + bb.w);
            *(float4*)&g_C1[row * N1 + col] = v;
        }
    }
}

// ---------------- SpMM1 (pull, warp/node): H[r] = relu(h_pre[r] + sum w*y1[c]) -------
__global__ __launch_bounds__(256) void k_spmm1() {
    const int wid  = threadIdx.x >> 5;
    const int lane = threadIdx.x & 31;
    const int r = blockIdx.x * 8 + wid;
    if (r >= NN) return;

    const int e0 = g_off[r];
    const int d  = g_cur[r];     // actual bucketed count
    float acc0 = 0.f, acc1 = 0.f;

    for (int base = 0; base < d; base += 32) {
        int   cl = 0;  float wl = 0.f;
        int   j  = base + lane;
        if (j < d) { cl = g_col[e0 + j]; wl = g_w[e0 + j]; }
        int lim = min(32, d - base);
        for (int jj = 0; jj < lim; jj++) {
            int   c = __shfl_sync(0xffffffffu, cl, jj);
            float w = __shfl_sync(0xffffffffu, wl, jj);
            const float* __restrict__ src = &g_C1[c * N1 + FH];
            acc0 += w * __ldg(&src[lane]);
            acc1 += w * __ldg(&src[32 + lane]);
        }
    }
    const float* pre = &g_C1[r * N1];
    g_H[r * FH + lane]      = fmaxf(pre[lane]      + acc0, 0.f);
    g_H[r * FH + 32 + lane] = fmaxf(pre[32 + lane] + acc1, 0.f);
}

// ---------------- GEMM2: out_pre = H@W2_0 + b2 -> d_out ; y2 = H@W2_1 ----------------
__global__ __launch_bounds__(320) void k_gemm2(const float* __restrict__ W20,
                                               const float* __restrict__ W21,
                                               const float* __restrict__ b2,
                                               float* __restrict__ out) {
    __shared__ float hs[64][FH];   // 16 KB
    __shared__ float ws[FH][N2];   // 20 KB
    const int t  = threadIdx.x;    // 320
    const int r0 = blockIdx.x * 64;

    for (int idx = t; idx < FH * N2; idx += 320) {
        int k = idx / N2;
        int j = idx % N2;
        ws[k][j] = (j < FOUT) ? W20[k * FOUT + j] : W21[k * FOUT + (j - FOUT)];
    }
    for (int idx = t; idx < 64 * FH; idx += 320) {
        int r = idx >> 6;
        int k = idx & 63;
        int row = r0 + r;
        hs[r][k] = (row < NN) ? g_H[row * FH + k] : 0.f;
    }
    __syncthreads();

    const int cg = t % 20;
    const int rg = t / 20;
    float acc[4][4];
#pragma unroll
    for (int i = 0; i < 4; i++)
#pragma unroll
        for (int j = 0; j < 4; j++) acc[i][j] = 0.f;

#pragma unroll 4
    for (int k = 0; k < FH; k++) {
        float4 w = *(const float4*)&ws[k][cg * 4];
#pragma unroll
        for (int i = 0; i < 4; i++) {
            float a = hs[rg * 4 + i][k];
            acc[i][0] += a * w.x; acc[i][1] += a * w.y;
            acc[i][2] += a * w.z; acc[i][3] += a * w.w;
        }
    }

    const int col = cg * 4;
#pragma unroll
    for (int i = 0; i < 4; i++) {
        int row = r0 + rg * 4 + i;
        if (row >= NN) continue;
        if (col < FOUT) {
            float4 bb = *(const float4*)&b2[col];
            float4 v = make_float4(acc[i][0] + bb.x, acc[i][1] + bb.y,
                                   acc[i][2] + bb.z, acc[i][3] + bb.w);
            *(float4*)&out[row * FOUT + col] = v;
        } else {
            float4 v = make_float4(acc[i][0], acc[i][1], acc[i][2], acc[i][3]);
            *(float4*)&g_y2[row * FOUT + (col - FOUT)] = v;
        }
    }
}

// ---------------- SpMM2 (pull, warp/node): out[r] += sum w*y2[c] ---------------------
__global__ __launch_bounds__(256) void k_spmm2(float* __restrict__ out) {
    const int wid  = threadIdx.x >> 5;
    const int lane = threadIdx.x & 31;
    const int r = blockIdx.x * 8 + wid;
    if (r >= NN) return;

    const int e0 = g_off[r];
    const int d  = g_cur[r];
    float acc0 = 0.f, acc1 = 0.f;

    for (int base = 0; base < d; base += 32) {
        int   cl = 0;  float wl = 0.f;
        int   j  = base + lane;
        if (j < d) { cl = g_col[e0 + j]; wl = g_w[e0 + j]; }
        int lim = min(32, d - base);
        for (int jj = 0; jj < lim; jj++) {
            int   c = __shfl_sync(0xffffffffu, cl, jj);
            float w = __shfl_sync(0xffffffffu, wl, jj);
            const float* __restrict__ src = &g_y2[c * FOUT];
            acc0 += w * __ldg(&src[lane]);
            if (lane < FOUT - 32) acc1 += w * __ldg(&src[32 + lane]);
        }
    }
    float* o = &out[r * FOUT];
    o[lane] += acc0;
    if (lane < FOUT - 32) o[32 + lane] += acc1;
}

extern "C" void kernel_launch(void* const* d_in, const int* in_sizes, int n_in,
                              void* d_out, int out_size) {
    const float* x   = (const float*)d_in[0];
    const void*  ei  = d_in[1];
    const float* W10 = (const float*)d_in[2];
    const float* W11 = (const float*)d_in[3];
    const float* b1  = (const float*)d_in[4];
    const float* W20 = (const float*)d_in[5];
    const float* W21 = (const float*)d_in[6];
    const float* b2  = (const float*)d_in[7];
    float* out = (float*)d_out;

    k_detect<<<1, 32>>>(ei);
    k_zero  <<<(NN + 255) / 256, 256>>>();
    k_deg   <<<(NE + 255) / 256, 256>>>(ei);
    k_dis   <<<(NN + 255) / 256, 256>>>();
    k_scanA <<<NBLK_SCAN, SCAN_B>>>();
    k_scanB <<<1, 32>>>();
    k_scanC <<<(NN + 255) / 256, 256>>>();
    k_bucket<<<(NE + 255) / 256, 256>>>(ei);
    k_gemm1 <<<(NN + 63) / 64, 256>>>(x, W10, W11, b1);
    k_spmm1 <<<(NN + 7) / 8, 256>>>();
    k_gemm2 <<<(NN + 63) / 64, 320>>>(W20, W21, b2, out);
    k_spmm2 <<<(NN + 7) / 8, 256>>>(out);
}